// round 2
// baseline (speedup 1.0000x reference)
#include <cuda_runtime.h>

#define N       4096
#define THREADS 256
#define PAD(i)  ((i) + ((i) >> 5))
#define SMW     (4096 + 128)

__global__ __launch_bounds__(THREADS)
void fwht_kernel(const float* __restrict__ x,
                 const float* __restrict__ s,
                 float* __restrict__ out)
{
    __shared__ float smA[SMW];
    __shared__ float smB[SMW];

    const int row  = blockIdx.x;
    const int t    = threadIdx.x;
    const int lane = t & 31;
    const int w    = t >> 5;

    // ---- load 16 contiguous elements, apply sign ----
    float v[16];
    const float4* xr = reinterpret_cast<const float4*>(x + (size_t)row * N + t * 16);
    const float4* sr = reinterpret_cast<const float4*>(s + t * 16);
    #pragma unroll
    for (int j = 0; j < 4; j++) {
        float4 a = xr[j];
        float4 b = sr[j];
        v[4*j+0] = a.x * b.x;
        v[4*j+1] = a.y * b.y;
        v[4*j+2] = a.z * b.z;
        v[4*j+3] = a.w * b.w;
    }

    // ---- stage 1: FWHT over i[3:0] (regs), 4 levels ----
    #pragma unroll
    for (int m = 1; m < 16; m <<= 1) {
        #pragma unroll
        for (int r = 0; r < 16; r++) {
            if ((r & m) == 0) {
                float a = v[r], b = v[r | m];
                v[r]     = a + b;
                v[r | m] = a - b;
            }
        }
    }

    // ---- transpose A: bring i[7:4] into registers ----
    // write layout: i = t*16 + r  (i[3:0]=r, i[8:4]=lane, i[11:9]=w)
    #pragma unroll
    for (int r = 0; r < 16; r++) {
        int i = t * 16 + r;
        smA[PAD(i)] = v[r];
    }
    __syncthreads();

    // middle layout: i[3:0]=lane[3:0], i[7:4]=r', i[8]=w[0], i[9]=lane[4], i[11:10]=w[2:1]
    const int base2 = ((w >> 1) << 10) | ((lane >> 4) << 9) | ((w & 1) << 8) | (lane & 15);
    float u[16];
    #pragma unroll
    for (int r = 0; r < 16; r++)
        u[r] = smA[PAD(base2 | (r << 4))];

    // ---- stage 2: FWHT over i[7:4] (regs), 4 levels ----
    #pragma unroll
    for (int m = 1; m < 16; m <<= 1) {
        #pragma unroll
        for (int r = 0; r < 16; r++) {
            if ((r & m) == 0) {
                float a = u[r], b = u[r | m];
                u[r]     = a + b;
                u[r | m] = a - b;
            }
        }
    }

    // ---- transpose B: bring i[11:8] into registers ----
    #pragma unroll
    for (int r = 0; r < 16; r++)
        smB[PAD(base2 | (r << 4))] = u[r];
    __syncthreads();

    // final layout: i[4:0]=lane, i[7:5]=w, i[11:8]=r''
    const int base3 = (w << 5) | lane;
    float z[16];
    #pragma unroll
    for (int r = 0; r < 16; r++)
        z[r] = smB[PAD(base3 | (r << 8))];

    // ---- stage 3: FWHT over i[11:8] (regs), 4 levels ----
    #pragma unroll
    for (int m = 1; m < 16; m <<= 1) {
        #pragma unroll
        for (int r = 0; r < 16; r++) {
            if ((r & m) == 0) {
                float a = z[r], b = z[r | m];
                z[r]     = a + b;
                z[r | m] = a - b;
            }
        }
    }

    // ---- scaled, fully-coalesced store (32 contiguous floats per warp per r) ----
    const float scale = 0.015625f;   // 1/sqrt(4096)
    float* orow = out + (size_t)row * N;
    #pragma unroll
    for (int r = 0; r < 16; r++)
        orow[base3 | (r << 8)] = z[r] * scale;
}

extern "C" void kernel_launch(void* const* d_in, const int* in_sizes, int n_in,
                              void* d_out, int out_size)
{
    const float* x = (const float*)d_in[0];
    const float* s = (const float*)d_in[1];
    float* out     = (float*)d_out;

    const int rows = in_sizes[0] / N;   // 16384
    fwht_kernel<<<rows, THREADS>>>(x, s, out);
}

// round 4
// speedup vs baseline: 1.2788x; 1.2788x over previous
#include <cuda_runtime.h>

#define N       4096
#define THREADS 256
#define PAD(i)  ((i) + ((i) >> 5))
#define SMW     (4096 + 128)

__global__ __launch_bounds__(THREADS)
void fwht_kernel(const float* __restrict__ x,
                 const float* __restrict__ s,
                 float* __restrict__ out)
{
    __shared__ float sm[SMW];

    const int row  = blockIdx.x;
    const int t    = threadIdx.x;
    const int lane = t & 31;
    const int w    = t >> 5;

    // ---- load 16 contiguous elements, apply sign ----
    // initial layout: i[3:0]=reg, i[8:4]=lane, i[11:9]=w
    float v[16];
    const float4* xr = reinterpret_cast<const float4*>(x + (size_t)row * N + t * 16);
    const float4* sr = reinterpret_cast<const float4*>(s + t * 16);
    #pragma unroll
    for (int j = 0; j < 4; j++) {
        float4 a = xr[j];
        float4 b = sr[j];
        v[4*j+0] = a.x * b.x;
        v[4*j+1] = a.y * b.y;
        v[4*j+2] = a.z * b.z;
        v[4*j+3] = a.w * b.w;
    }

    // ---- stage 1: FWHT over reg bits i[3:0], 4 levels ----
    #pragma unroll
    for (int m = 1; m < 16; m <<= 1) {
        #pragma unroll
        for (int r = 0; r < 16; r++) {
            if ((r & m) == 0) {
                float a = v[r], b = v[r | m];
                v[r]     = a + b;
                v[r | m] = a - b;
            }
        }
    }

    // ---- stage 2: 5 half-exchange levels over lane bits (i[8:4]) ----
    // Each level: 8 SHFL instead of 16; swaps roles of reg bit 3 and lane bit m.
    // After all 5: lane bit k = i[3+k] (k=0..4), reg3 = i[8], regs[2:0] = i[2:0].
    #pragma unroll
    for (int m = 1; m < 32; m <<= 1) {
        const bool  lo  = (lane & m) == 0;
        const float sgn = lo ? 1.0f : -1.0f;
        #pragma unroll
        for (int r = 0; r < 8; r++) {
            float keep = lo ? v[r]     : v[r + 8];
            float send = lo ? v[r + 8] : v[r];
            float recv = __shfl_xor_sync(0xffffffffu, send, m);
            // lo: keep=A_low, recv=B_low -> (A+B, A-B)
            // hi: keep=B_high, recv=A_high -> (A+B, (A-B) = (keep-recv)*-1)
            v[r]     = keep + recv;
            v[r + 8] = (keep - recv) * sgn;
        }
    }

    // ---- transpose: write at logical i, padded (conflict-free, verified) ----
    // current: i = (w<<9) | (reg3<<8) | (lane<<3) | reg[2:0]
    const int wbase = (w << 9) | (lane << 3);
    #pragma unroll
    for (int r = 0; r < 16; r++) {
        int i = wbase | ((r >> 3) << 8) | (r & 7);
        sm[PAD(i)] = v[r];
    }
    __syncthreads();

    // read: rp[2:0] = i[11:9] (untransformed), rp3 = i[8] (done),
    //       w = i[7:5], lane = i[4:0]  -> lane-contiguous (conflict-free)
    const int rbase = (w << 5) | lane;
    float u[16];
    #pragma unroll
    for (int rp = 0; rp < 16; rp++) {
        int i = ((rp & 7) << 9) | ((rp >> 3) << 8) | rbase;
        u[rp] = sm[PAD(i)];
    }

    // ---- stage 3: FWHT over i[11:9] = rp bits [2:0], 3 levels ----
    #pragma unroll
    for (int m = 1; m < 8; m <<= 1) {
        #pragma unroll
        for (int rp = 0; rp < 16; rp++) {
            if ((rp & m) == 0) {
                float a = u[rp], b = u[rp | m];
                u[rp]     = a + b;
                u[rp | m] = a - b;
            }
        }
    }

    // ---- scaled, fully-coalesced store (32 contiguous floats per warp per rp) ----
    const float scale = 0.015625f;   // 1/sqrt(4096)
    float* orow = out + (size_t)row * N;
    #pragma unroll
    for (int rp = 0; rp < 16; rp++) {
        int i = ((rp & 7) << 9) | ((rp >> 3) << 8) | rbase;
        orow[i] = u[rp] * scale;
    }
}

extern "C" void kernel_launch(void* const* d_in, const int* in_sizes, int n_in,
                              void* d_out, int out_size)
{
    const float* x = (const float*)d_in[0];
    const float* s = (const float*)d_in[1];
    float* out     = (float*)d_out;

    const int rows = in_sizes[0] / N;   // 16384
    fwht_kernel<<<rows, THREADS>>>(x, s, out);
}

// round 6
// speedup vs baseline: 1.6177x; 1.2650x over previous
#include <cuda_runtime.h>

#define N       4096
#define THREADS 256
#define PAD(i)  ((i) + ((i) >> 5))
#define SMW     (4096 + 128)

// Sign bitmask: bit e of g_smask[e>>5] = (s[e] < 0). 128 words, built per call.
__device__ unsigned g_smask[N / 32];

__global__ void pack_signs(const float* __restrict__ s)
{
    int i = blockIdx.x * blockDim.x + threadIdx.x;
    unsigned b = __ballot_sync(0xffffffffu, __float_as_int(s[i]) < 0);
    if ((threadIdx.x & 31) == 0) g_smask[i >> 5] = b;
}

__global__ __launch_bounds__(THREADS)
void fwht_kernel(const float* __restrict__ x,
                 float* __restrict__ out)
{
    __shared__ float sm[SMW];

    const int row  = blockIdx.x;
    const int t    = threadIdx.x;
    const int lane = t & 31;
    const int w    = t >> 5;

    // ---- load 16 contiguous elements ----
    // initial layout: i[3:0]=reg, i[8:4]=lane, i[11:9]=w
    float v[16];
    const float4* xr = reinterpret_cast<const float4*>(x + (size_t)row * N + t * 16);
    #pragma unroll
    for (int j = 0; j < 4; j++) {
        float4 a = xr[j];
        v[4*j+0] = a.x; v[4*j+1] = a.y; v[4*j+2] = a.z; v[4*j+3] = a.w;
    }

    // ---- apply signs via bitmask XOR (s = ±1 exactly) ----
    // elements t*16+k  ->  word t>>1, bits (t&1)*16 + k
    {
        const unsigned m = g_smask[t >> 1] >> ((t & 1) << 4);
        #pragma unroll
        for (int k = 0; k < 16; k++)
            v[k] = __int_as_float(__float_as_int(v[k]) ^
                                  (int)((m << (31 - k)) & 0x80000000u));
    }

    // ---- stage 1: FWHT over reg bits i[3:0], 4 levels ----
    #pragma unroll
    for (int m = 1; m < 16; m <<= 1) {
        #pragma unroll
        for (int r = 0; r < 16; r++) {
            if ((r & m) == 0) {
                float a = v[r], b = v[r | m];
                v[r]     = a + b;
                v[r | m] = a - b;
            }
        }
    }

    // ---- stage 2: 4 half-exchange levels over lane bits i[7:4] ----
    // Each level swaps roles of reg bit 3 and the lane bit.
    // After: regs[2:0]=i[2:0], reg3=i[7], lane={i3,i4,i5,i6,i8}; i[8],i[11:9] remain.
    #pragma unroll
    for (int m = 1; m < 16; m <<= 1) {
        const bool  lo  = (lane & m) == 0;
        const float sgn = lo ? 1.0f : -1.0f;
        #pragma unroll
        for (int r = 0; r < 8; r++) {
            float keep = lo ? v[r]     : v[r + 8];
            float send = lo ? v[r + 8] : v[r];
            float recv = __shfl_xor_sync(0xffffffffu, send, m);
            v[r]     = keep + recv;
            v[r + 8] = (keep - recv) * sgn;
        }
    }

    // ---- transpose: smem address a = (w<<9)|(i7<<8)|(i8<<7)|(i6..i3<<3)|i[2:0]
    // (i7 and i8 swapped in the address map for conflict-free banking; verified:
    //  write bank = 8*L0+16*L1+1*L2+2*L3+4*L4+const -> 32 distinct; read = lane+const)
    const int wbase = (w << 9) | ((lane >> 4) << 7) | ((lane & 15) << 3);
    #pragma unroll
    for (int r = 0; r < 16; r++) {
        int a = wbase | ((r >> 3) << 8) | (r & 7);
        sm[PAD(a)] = v[r];
    }
    __syncthreads();

    // read: rp[2:0]=i[11:9], rp3=i[8], w'=i[7:5], lane'=i[4:0]
    const int rbase = ((w >> 2) << 8) | ((w & 3) << 5) | lane;
    float u[16];
    #pragma unroll
    for (int rp = 0; rp < 16; rp++) {
        int a = ((rp & 7) << 9) | ((rp >> 3) << 7) | rbase;
        u[rp] = sm[PAD(a)];
    }

    // ---- stage 3: FWHT over remaining bits {i[11:9], i[8]} = all 4 rp bits ----
    #pragma unroll
    for (int m = 1; m < 16; m <<= 1) {
        #pragma unroll
        for (int rp = 0; rp < 16; rp++) {
            if ((rp & m) == 0) {
                float a = u[rp], b = u[rp | m];
                u[rp]     = a + b;
                u[rp | m] = a - b;
            }
        }
    }

    // ---- scaled, fully-coalesced store ----
    const float scale = 0.015625f;   // 1/sqrt(4096)
    float* orow = out + (size_t)row * N;
    #pragma unroll
    for (int rp = 0; rp < 16; rp++) {
        int o = ((rp & 7) << 9) | ((rp >> 3) << 8) | (w << 5) | lane;
        orow[o] = u[rp] * scale;
    }
}

extern "C" void kernel_launch(void* const* d_in, const int* in_sizes, int n_in,
                              void* d_out, int out_size)
{
    const float* x = (const float*)d_in[0];
    const float* s = (const float*)d_in[1];
    float* out     = (float*)d_out;

    pack_signs<<<N / 1024, 1024>>>(s);

    const int rows = in_sizes[0] / N;   // 16384
    fwht_kernel<<<rows, THREADS>>>(x, out);
}